// round 1
// baseline (speedup 1.0000x reference)
#include <cuda_runtime.h>
#include <math.h>

#define HIDK 1024
#define MTOK 4096
#define LSEQ 2048
#define NHEAD 16
#define HDIM 64

#define BM 128
#define BN 128
#define BK 8

// ---------------- scratch (device globals; no allocations) ----------------
__device__ float g_q[MTOK * HIDK];
__device__ float g_k[MTOK * HIDK];
__device__ float g_v[MTOK * HIDK];
__device__ float g_xg[MTOK * HIDK];
__device__ float g_gk[MTOK * HIDK];
__device__ float g_att[MTOK * HIDK];
__device__ float g_y[MTOK * HIDK];
__device__ float g_t[MTOK * 16];

// ---------------- fp32 tiled GEMM: C[M,1024] = A[M,1024] @ B[1024,1024] ---
__device__ __forceinline__ void gemm_body(const float* __restrict__ A,
                                          const float* __restrict__ B,
                                          float* __restrict__ C) {
    __shared__ float As[BK][BM + 4];
    __shared__ float Bs[BK][BN];
    int tid = threadIdx.x;
    int brow = blockIdx.y * BM;
    int bcol = blockIdx.x * BN;

    float acc[8][8];
#pragma unroll
    for (int i = 0; i < 8; i++)
#pragma unroll
        for (int j = 0; j < 8; j++) acc[i][j] = 0.f;

    int ty = tid >> 4, tx = tid & 15;
    int row = ty * 8, col = tx * 8;
    int lar = tid >> 1, lac = (tid & 1) * 4;
    int lbr = tid >> 5, lbc = (tid & 31) * 4;

    for (int k0 = 0; k0 < HIDK; k0 += BK) {
        float4 a4 = *(const float4*)(A + (size_t)(brow + lar) * HIDK + k0 + lac);
        float4 b4 = *(const float4*)(B + (size_t)(k0 + lbr) * HIDK + bcol + lbc);
        As[lac + 0][lar] = a4.x;
        As[lac + 1][lar] = a4.y;
        As[lac + 2][lar] = a4.z;
        As[lac + 3][lar] = a4.w;
        *(float4*)&Bs[lbr][lbc] = b4;
        __syncthreads();
#pragma unroll
        for (int kk = 0; kk < BK; kk++) {
            float a[8], b[8];
            *(float4*)&a[0] = *(const float4*)&As[kk][row];
            *(float4*)&a[4] = *(const float4*)&As[kk][row + 4];
            *(float4*)&b[0] = *(const float4*)&Bs[kk][col];
            *(float4*)&b[4] = *(const float4*)&Bs[kk][col + 4];
#pragma unroll
            for (int i = 0; i < 8; i++)
#pragma unroll
                for (int j = 0; j < 8; j++) acc[i][j] = fmaf(a[i], b[j], acc[i][j]);
        }
        __syncthreads();
    }
#pragma unroll
    for (int i = 0; i < 8; i++) {
        float* cp = C + (size_t)(brow + row + i) * HIDK + bcol + col;
        *(float4*)cp = make_float4(acc[i][0], acc[i][1], acc[i][2], acc[i][3]);
        *(float4*)(cp + 4) = make_float4(acc[i][4], acc[i][5], acc[i][6], acc[i][7]);
    }
}

// q,k,v,xg = x @ {Wq,Wk,Wv,Wg}
__global__ void __launch_bounds__(256) sgemm4_kernel(const float* __restrict__ x,
                                                     const float* __restrict__ Wq,
                                                     const float* __restrict__ Wk,
                                                     const float* __restrict__ Wv,
                                                     const float* __restrict__ Wg) {
    const float* B;
    float* C;
    switch (blockIdx.z) {
        case 0: B = Wq; C = g_q; break;
        case 1: B = Wk; C = g_k; break;
        case 2: B = Wv; C = g_v; break;
        default: B = Wg; C = g_xg; break;
    }
    gemm_body(x, B, C);
}

// out = y @ Wout
__global__ void __launch_bounds__(256) sgemm_out_kernel(const float* __restrict__ Wout,
                                                        float* __restrict__ out) {
    gemm_body(g_y, Wout, out);
}

// ---------------- low-rank gate: t = x @ Wgk1  ([4096,16]) -----------------
__global__ void __launch_bounds__(256) lr1_kernel(const float* __restrict__ x,
                                                  const float* __restrict__ W1) {
    int tid = threadIdx.x;
    int r = tid & 15;
    int ml = tid >> 4;
    int m = blockIdx.x * 16 + ml;
    const float* xr = x + (size_t)m * HIDK;
    float acc = 0.f;
#pragma unroll 4
    for (int kk = 0; kk < HIDK; kk++) acc = fmaf(xr[kk], W1[kk * 16 + r], acc);
    g_t[m * 16 + r] = acc;
}

// gk = log_sigmoid(t @ Wgk2 + b) / 16   ([4096,1024])
__global__ void __launch_bounds__(256) lr2_kernel(const float* __restrict__ W2,
                                                  const float* __restrict__ bias) {
    int m = blockIdx.x;
    __shared__ float tm[16];
    if (threadIdx.x < 16) tm[threadIdx.x] = g_t[m * 16 + threadIdx.x];
    __syncthreads();
    for (int n = threadIdx.x; n < HIDK; n += 256) {
        float a = bias[n];
#pragma unroll
        for (int r = 0; r < 16; r++) a = fmaf(tm[r], W2[r * HIDK + n], a);
        // stable log_sigmoid
        float ls = fminf(a, 0.f) - log1pf(__expf(-fabsf(a)));
        g_gk[(size_t)m * HIDK + n] = ls * 0.0625f;
    }
}

// ---------------- recurrent scan: one block per (b,h) ----------------------
// state[v,k] 64x64; 512 threads: thread = (v=tid>>3, 8 k-elems at (tid&7)*8)
#define CH 32
__global__ void __launch_bounds__(512) scan_kernel() {
    int bh = blockIdx.x;
    int b = bh >> 4, h = bh & 15;
    __shared__ float sq[CH][64], sk[CH][64], sv[CH][64], sg[CH][64];
    int tid = threadIdx.x;
    int vr = tid >> 3;
    int kg = (tid & 7) << 3;
    float st[8];
#pragma unroll
    for (int j = 0; j < 8; j++) st[j] = 0.f;

    for (int c = 0; c < LSEQ / CH; c++) {
        // cooperative chunk load: 2048 elems per array, 4 per thread
#pragma unroll
        for (int i = 0; i < (CH * 64) / 512; i++) {
            int e = tid + i * 512;
            int s = e >> 6, d = e & 63;
            size_t gi = ((size_t)(b * LSEQ + c * CH + s)) * HIDK + h * HDIM + d;
            sq[s][d] = g_q[gi];
            sk[s][d] = g_k[gi];
            sv[s][d] = g_v[gi];
            sg[s][d] = g_gk[gi];
        }
        __syncthreads();
#pragma unroll 4
        for (int s = 0; s < CH; s++) {
            float gate = __expf(sg[s][vr]);
            float vv = sv[s][vr];
            float4 ka = *(const float4*)&sk[s][kg];
            float4 kb = *(const float4*)&sk[s][kg + 4];
            float4 qa = *(const float4*)&sq[s][kg];
            float4 qb = *(const float4*)&sq[s][kg + 4];
            float acc;
            st[0] = fmaf(st[0], gate, vv * ka.x); acc = st[0] * qa.x;
            st[1] = fmaf(st[1], gate, vv * ka.y); acc = fmaf(st[1], qa.y, acc);
            st[2] = fmaf(st[2], gate, vv * ka.z); acc = fmaf(st[2], qa.z, acc);
            st[3] = fmaf(st[3], gate, vv * ka.w); acc = fmaf(st[3], qa.w, acc);
            st[4] = fmaf(st[4], gate, vv * kb.x); acc = fmaf(st[4], qb.x, acc);
            st[5] = fmaf(st[5], gate, vv * kb.y); acc = fmaf(st[5], qb.y, acc);
            st[6] = fmaf(st[6], gate, vv * kb.z); acc = fmaf(st[6], qb.z, acc);
            st[7] = fmaf(st[7], gate, vv * kb.w); acc = fmaf(st[7], qb.w, acc);
            acc += __shfl_xor_sync(0xffffffffu, acc, 1);
            acc += __shfl_xor_sync(0xffffffffu, acc, 2);
            acc += __shfl_xor_sync(0xffffffffu, acc, 4);
            if ((tid & 7) == 0)
                g_att[((size_t)(b * LSEQ + c * CH + s)) * HIDK + h * HDIM + vr] = acc;
        }
        __syncthreads();
    }
}

// ---------------- LayerNorm + SiLU output gate ------------------------------
__global__ void __launch_bounds__(256) ln_gate_kernel(const float* __restrict__ gamma,
                                                      const float* __restrict__ beta) {
    int row = blockIdx.x;
    int tid = threadIdx.x;
    const float* a = g_att + (size_t)row * HIDK;
    float vals[4];
    float s = 0.f, s2 = 0.f;
#pragma unroll
    for (int i = 0; i < 4; i++) {
        vals[i] = a[i * 256 + tid];
        s += vals[i];
        s2 = fmaf(vals[i], vals[i], s2);
    }
#pragma unroll
    for (int o = 16; o; o >>= 1) {
        s += __shfl_xor_sync(0xffffffffu, s, o);
        s2 += __shfl_xor_sync(0xffffffffu, s2, o);
    }
    __shared__ float rs[8], rs2[8];
    int warp = tid >> 5;
    if ((tid & 31) == 0) { rs[warp] = s; rs2[warp] = s2; }
    __syncthreads();
    s = 0.f; s2 = 0.f;
#pragma unroll
    for (int w = 0; w < 8; w++) { s += rs[w]; s2 += rs2[w]; }
    float mean = s * (1.f / HIDK);
    float var = s2 * (1.f / HIDK) - mean * mean;
    float rstd = rsqrtf(var + 1e-5f);
#pragma unroll
    for (int i = 0; i < 4; i++) {
        int col = i * 256 + tid;
        float gv = g_xg[(size_t)row * HIDK + col];
        float sil = gv / (1.f + __expf(-gv));
        g_y[(size_t)row * HIDK + col] =
            ((vals[i] - mean) * rstd * gamma[col] + beta[col]) * sil;
    }
}

// ---------------- launch --------------------------------------------------
extern "C" void kernel_launch(void* const* d_in, const int* in_sizes, int n_in,
                              void* d_out, int out_size) {
    const float* x = (const float*)d_in[0];
    const float* Wq = (const float*)d_in[1];
    const float* Wk = (const float*)d_in[2];
    const float* Wv = (const float*)d_in[3];
    const float* Wg = (const float*)d_in[4];
    const float* Wgk1 = (const float*)d_in[5];
    const float* Wgk2 = (const float*)d_in[6];
    const float* bgk2 = (const float*)d_in[7];
    const float* gamma = (const float*)d_in[8];
    const float* beta = (const float*)d_in[9];
    const float* Wout = (const float*)d_in[10];
    float* out = (float*)d_out;

    dim3 gridG(HIDK / BN, MTOK / BM, 4);
    sgemm4_kernel<<<gridG, 256>>>(x, Wq, Wk, Wv, Wg);
    lr1_kernel<<<MTOK / 16, 256>>>(x, Wgk1);
    lr2_kernel<<<MTOK, 256>>>(Wgk2, bgk2);
    scan_kernel<<<32, 512>>>();
    ln_gate_kernel<<<MTOK, 256>>>(gamma, beta);
    dim3 gridO(HIDK / BN, MTOK / BM, 1);
    sgemm_out_kernel<<<gridO, 256>>>(Wout, out);
}

// round 2
// speedup vs baseline: 1.6668x; 1.6668x over previous
#include <cuda_runtime.h>
#include <math.h>

#define HIDK 1024
#define MTOK 4096
#define LSEQ 2048
#define NHEAD 16
#define HDIM 64
#define CT 64
#define NCH (LSEQ / CT)
#define PD 68

#define BM 128
#define BN 128
#define BK 8

// ---------------- scratch (device globals; no allocations) ----------------
__device__ float g_q[MTOK * HIDK];
__device__ float g_k[MTOK * HIDK];
__device__ float g_v[MTOK * HIDK];
__device__ float g_xg[MTOK * HIDK];
__device__ float g_gk[MTOK * HIDK];
__device__ float g_att[MTOK * HIDK];
__device__ float g_y[MTOK * HIDK];
__device__ float g_t[MTOK * 16];
__device__ float g_expD[MTOK * HIDK];                 // exp(cumsum g) per chunk
__device__ float g_P[32 * NCH * HDIM * HDIM];         // per-chunk summary
__device__ float g_S[32 * NCH * HDIM * HDIM];         // chunk-start states

// ---------------- fp32 tiled GEMM (double-buffered) ------------------------
__device__ __forceinline__ void gemm_body(const float* __restrict__ A,
                                          const float* __restrict__ B,
                                          float* __restrict__ C) {
    __shared__ float As[2][BK][BM + 4];
    __shared__ float Bs[2][BK][BN];
    int tid = threadIdx.x;
    int brow = blockIdx.y * BM;
    int bcol = blockIdx.x * BN;

    float acc[8][8];
#pragma unroll
    for (int i = 0; i < 8; i++)
#pragma unroll
        for (int j = 0; j < 8; j++) acc[i][j] = 0.f;

    int ty = tid >> 4, tx = tid & 15;
    int row = ty * 8, col = tx * 8;
    int lar = tid >> 1, lac = (tid & 1) * 4;
    int lbr = tid >> 5, lbc = (tid & 31) * 4;

    float4 a4 = *(const float4*)(A + (size_t)(brow + lar) * HIDK + lac);
    float4 b4 = *(const float4*)(B + (size_t)lbr * HIDK + bcol + lbc);
    As[0][lac + 0][lar] = a4.x;
    As[0][lac + 1][lar] = a4.y;
    As[0][lac + 2][lar] = a4.z;
    As[0][lac + 3][lar] = a4.w;
    *(float4*)&Bs[0][lbr][lbc] = b4;
    __syncthreads();

    int sbuf = 0;
    for (int k0 = 0; k0 < HIDK; k0 += BK) {
        if (k0 + BK < HIDK) {
            a4 = *(const float4*)(A + (size_t)(brow + lar) * HIDK + k0 + BK + lac);
            b4 = *(const float4*)(B + (size_t)(k0 + BK + lbr) * HIDK + bcol + lbc);
        }
#pragma unroll
        for (int kk = 0; kk < BK; kk++) {
            float a[8], b[8];
            *(float4*)&a[0] = *(const float4*)&As[sbuf][kk][row];
            *(float4*)&a[4] = *(const float4*)&As[sbuf][kk][row + 4];
            *(float4*)&b[0] = *(const float4*)&Bs[sbuf][kk][col];
            *(float4*)&b[4] = *(const float4*)&Bs[sbuf][kk][col + 4];
#pragma unroll
            for (int i = 0; i < 8; i++)
#pragma unroll
                for (int j = 0; j < 8; j++) acc[i][j] = fmaf(a[i], b[j], acc[i][j]);
        }
        if (k0 + BK < HIDK) {
            As[sbuf ^ 1][lac + 0][lar] = a4.x;
            As[sbuf ^ 1][lac + 1][lar] = a4.y;
            As[sbuf ^ 1][lac + 2][lar] = a4.z;
            As[sbuf ^ 1][lac + 3][lar] = a4.w;
            *(float4*)&Bs[sbuf ^ 1][lbr][lbc] = b4;
        }
        __syncthreads();
        sbuf ^= 1;
    }
#pragma unroll
    for (int i = 0; i < 8; i++) {
        float* cp = C + (size_t)(brow + row + i) * HIDK + bcol + col;
        *(float4*)cp = make_float4(acc[i][0], acc[i][1], acc[i][2], acc[i][3]);
        *(float4*)(cp + 4) = make_float4(acc[i][4], acc[i][5], acc[i][6], acc[i][7]);
    }
}

__global__ void __launch_bounds__(256) sgemm4_kernel(const float* __restrict__ x,
                                                     const float* __restrict__ Wq,
                                                     const float* __restrict__ Wk,
                                                     const float* __restrict__ Wv,
                                                     const float* __restrict__ Wg) {
    const float* B;
    float* C;
    switch (blockIdx.z) {
        case 0: B = Wq; C = g_q; break;
        case 1: B = Wk; C = g_k; break;
        case 2: B = Wv; C = g_v; break;
        default: B = Wg; C = g_xg; break;
    }
    gemm_body(x, B, C);
}

__global__ void __launch_bounds__(256) sgemm_out_kernel(const float* __restrict__ Wout,
                                                        float* __restrict__ out) {
    gemm_body(g_y, Wout, out);
}

// ---------------- low-rank gate path ---------------------------------------
__global__ void __launch_bounds__(256) lr1_kernel(const float* __restrict__ x,
                                                  const float* __restrict__ W1) {
    int tid = threadIdx.x;
    int r = tid & 15;
    int ml = tid >> 4;
    int m = blockIdx.x * 16 + ml;
    const float* xr = x + (size_t)m * HIDK;
    float acc = 0.f;
#pragma unroll 4
    for (int kk = 0; kk < HIDK; kk++) acc = fmaf(xr[kk], W1[kk * 16 + r], acc);
    g_t[m * 16 + r] = acc;
}

__global__ void __launch_bounds__(256) lr2_kernel(const float* __restrict__ W2,
                                                  const float* __restrict__ bias) {
    int m = blockIdx.x;
    __shared__ float tm[16];
    if (threadIdx.x < 16) tm[threadIdx.x] = g_t[m * 16 + threadIdx.x];
    __syncthreads();
    for (int n = threadIdx.x; n < HIDK; n += 256) {
        float a = bias[n];
#pragma unroll
        for (int r = 0; r < 16; r++) a = fmaf(tm[r], W2[r * HIDK + n], a);
        float ls = fminf(a, 0.f) - log1pf(__expf(-fabsf(a)));
        g_gk[(size_t)m * HIDK + n] = ls * 0.0625f;
    }
}

// ---------------- chunked GLA: kernel A (intra-chunk + summaries) ----------
// grid (chunk=32, bh=32), 256 threads, dynamic smem 6*64*68*4 bytes
__global__ void __launch_bounds__(256) chunk_kernel() {
    extern __shared__ float sm[];
    float* sQt = sm;                // [d][t]
    float* sKt = sm + 64 * PD;      // [d][s]
    float* sK  = sm + 2 * 64 * PD;  // [s][k]
    float* sU  = sm + 3 * 64 * PD;  // [s][v]
    float* sAV = sm + 4 * 64 * PD;  // V [t][v] then A^T [s][t]
    float* sED = sm + 5 * 64 * PD;  // g [t][v] then exp(D) [t][v]

    int c = blockIdx.x, bh = blockIdx.y;
    int b = bh >> 4, h = bh & 15;
    int tid = threadIdx.x;
    size_t rowbase = (size_t)(b * LSEQ + c * CT) * HIDK + h * HDIM;

#pragma unroll
    for (int i = 0; i < 4; i++) {
        int idx = tid + i * 256;
        int t = idx >> 4, c4 = (idx & 15) << 2;
        size_t gi = rowbase + (size_t)t * HIDK + c4;
        float4 q4 = *(const float4*)(g_q + gi);
        float4 k4 = *(const float4*)(g_k + gi);
        float4 v4 = *(const float4*)(g_v + gi);
        float4 gg = *(const float4*)(g_gk + gi);
        sQt[(c4 + 0) * PD + t] = q4.x;
        sQt[(c4 + 1) * PD + t] = q4.y;
        sQt[(c4 + 2) * PD + t] = q4.z;
        sQt[(c4 + 3) * PD + t] = q4.w;
        sKt[(c4 + 0) * PD + t] = k4.x;
        sKt[(c4 + 1) * PD + t] = k4.y;
        sKt[(c4 + 2) * PD + t] = k4.z;
        sKt[(c4 + 3) * PD + t] = k4.w;
        *(float4*)&sK[t * PD + c4] = k4;
        *(float4*)&sAV[t * PD + c4] = v4;
        *(float4*)&sED[t * PD + c4] = gg;
    }
    __syncthreads();

    // cumsum of g along t per v-channel; produce exp(D) and U = exp(-D)*v
    if (tid < 64) {
        float run = 0.f;
        for (int t = 0; t < CT; t++) {
            run += sED[t * PD + tid];
            sED[t * PD + tid] = __expf(run);
            sU[t * PD + tid] = __expf(-run) * sAV[t * PD + tid];
        }
    }
    __syncthreads();

    // write exp(D) out for kernels B & C
#pragma unroll
    for (int i = 0; i < 4; i++) {
        int idx = tid + i * 256;
        int t = idx >> 4, c4 = (idx & 15) << 2;
        *(float4*)(g_expD + rowbase + (size_t)t * HIDK + c4) =
            *(float4*)&sED[t * PD + c4];
    }

    // GEMM1: A[t,s] = q_t . k_s  -> store masked transposed into sAV as A^T[s][t]
    {
        int t0 = (tid & 15) << 2, s0 = (tid >> 4) << 2;
        float acc[4][4];
#pragma unroll
        for (int i = 0; i < 4; i++)
#pragma unroll
            for (int j = 0; j < 4; j++) acc[i][j] = 0.f;
        for (int d = 0; d < 64; d++) {
            float4 a = *(float4*)&sQt[d * PD + t0];
            float4 bb = *(float4*)&sKt[d * PD + s0];
            float av[4] = {a.x, a.y, a.z, a.w};
            float bv[4] = {bb.x, bb.y, bb.z, bb.w};
#pragma unroll
            for (int i = 0; i < 4; i++)
#pragma unroll
                for (int j = 0; j < 4; j++) acc[i][j] = fmaf(av[i], bv[j], acc[i][j]);
        }
#pragma unroll
        for (int j = 0; j < 4; j++) {
            int s = s0 + j;
            float4 o;
            o.x = (s <= t0 + 0) ? acc[0][j] : 0.f;
            o.y = (s <= t0 + 1) ? acc[1][j] : 0.f;
            o.z = (s <= t0 + 2) ? acc[2][j] : 0.f;
            o.w = (s <= t0 + 3) ? acc[3][j] : 0.f;
            *(float4*)&sAV[s * PD + t0] = o;
        }
    }
    __syncthreads();

    int r0 = (tid >> 4) << 2, c0 = (tid & 15) << 2;

    // GEMM2: o_intra[t,v] = exp(D_t[v]) * sum_s A^T[s][t] * U[s][v]
    {
        float acc[4][4];
#pragma unroll
        for (int i = 0; i < 4; i++)
#pragma unroll
            for (int j = 0; j < 4; j++) acc[i][j] = 0.f;
        for (int s = 0; s < CT; s++) {
            float4 a = *(float4*)&sAV[s * PD + r0];
            float4 bb = *(float4*)&sU[s * PD + c0];
            float av[4] = {a.x, a.y, a.z, a.w};
            float bv[4] = {bb.x, bb.y, bb.z, bb.w};
#pragma unroll
            for (int i = 0; i < 4; i++)
#pragma unroll
                for (int j = 0; j < 4; j++) acc[i][j] = fmaf(av[i], bv[j], acc[i][j]);
        }
#pragma unroll
        for (int i = 0; i < 4; i++) {
            int t = r0 + i;
            float4 e = *(float4*)&sED[t * PD + c0];
            float4 o = make_float4(acc[i][0] * e.x, acc[i][1] * e.y,
                                   acc[i][2] * e.z, acc[i][3] * e.w);
            *(float4*)(g_att + rowbase + (size_t)t * HIDK + c0) = o;
        }
    }

    // GEMM3: P[v,k] = exp(D_end[v]) * sum_s U[s][v] * K[s][k]
    {
        float acc[4][4];
#pragma unroll
        for (int i = 0; i < 4; i++)
#pragma unroll
            for (int j = 0; j < 4; j++) acc[i][j] = 0.f;
        for (int s = 0; s < CT; s++) {
            float4 a = *(float4*)&sU[s * PD + r0];
            float4 bb = *(float4*)&sK[s * PD + c0];
            float av[4] = {a.x, a.y, a.z, a.w};
            float bv[4] = {bb.x, bb.y, bb.z, bb.w};
#pragma unroll
            for (int i = 0; i < 4; i++)
#pragma unroll
                for (int j = 0; j < 4; j++) acc[i][j] = fmaf(av[i], bv[j], acc[i][j]);
        }
        size_t pbase = ((size_t)(bh * NCH + c)) << 12;  // *4096
#pragma unroll
        for (int i = 0; i < 4; i++) {
            float ev = sED[63 * PD + r0 + i];
            float4 o = make_float4(acc[i][0] * ev, acc[i][1] * ev,
                                   acc[i][2] * ev, acc[i][3] * ev);
            *(float4*)(g_P + pbase + ((size_t)(r0 + i) << 6) + c0) = o;
        }
    }
}

// ---------------- kernel B: scan over chunk states --------------------------
__global__ void __launch_bounds__(512) chunkscan_kernel() {
    int bh = blockIdx.x;
    int b = bh >> 4, h = bh & 15;
    int tid = threadIdx.x;
    int v = tid >> 3;
    int k0 = (tid & 7) << 3;
    float S[8];
#pragma unroll
    for (int j = 0; j < 8; j++) S[j] = 0.f;

    for (int c = 0; c < NCH; c++) {
        size_t base = (((size_t)(bh * NCH + c)) << 12) + ((size_t)v << 6) + k0;
        *(float4*)(g_S + base) = make_float4(S[0], S[1], S[2], S[3]);
        *(float4*)(g_S + base + 4) = make_float4(S[4], S[5], S[6], S[7]);
        float E = g_expD[((size_t)(b * LSEQ + c * CT + 63)) * HIDK + h * HDIM + v];
        float4 p0 = *(float4*)(g_P + base);
        float4 p1 = *(float4*)(g_P + base + 4);
        S[0] = fmaf(S[0], E, p0.x);
        S[1] = fmaf(S[1], E, p0.y);
        S[2] = fmaf(S[2], E, p0.z);
        S[3] = fmaf(S[3], E, p0.w);
        S[4] = fmaf(S[4], E, p1.x);
        S[5] = fmaf(S[5], E, p1.y);
        S[6] = fmaf(S[6], E, p1.z);
        S[7] = fmaf(S[7], E, p1.w);
    }
}

// ---------------- kernel C: inter-chunk output ------------------------------
// o[t,v] += exp(D_t[v]) * sum_k S0[v,k] q[t,k]
__global__ void __launch_bounds__(256) inter_kernel() {
    __shared__ float sQt[64 * PD];  // [k][t]
    __shared__ float sSt[64 * PD];  // [k][v]
    int c = blockIdx.x, bh = blockIdx.y;
    int b = bh >> 4, h = bh & 15;
    int tid = threadIdx.x;
    size_t rowbase = (size_t)(b * LSEQ + c * CT) * HIDK + h * HDIM;
    size_t sbase = ((size_t)(bh * NCH + c)) << 12;

#pragma unroll
    for (int i = 0; i < 4; i++) {
        int idx = tid + i * 256;
        int t = idx >> 4, c4 = (idx & 15) << 2;
        float4 q4 = *(const float4*)(g_q + rowbase + (size_t)t * HIDK + c4);
        sQt[(c4 + 0) * PD + t] = q4.x;
        sQt[(c4 + 1) * PD + t] = q4.y;
        sQt[(c4 + 2) * PD + t] = q4.z;
        sQt[(c4 + 3) * PD + t] = q4.w;
        // here t indexes the v-row of S, c4 the k columns
        float4 s4 = *(const float4*)(g_S + sbase + ((size_t)t << 6) + c4);
        sSt[(c4 + 0) * PD + t] = s4.x;
        sSt[(c4 + 1) * PD + t] = s4.y;
        sSt[(c4 + 2) * PD + t] = s4.z;
        sSt[(c4 + 3) * PD + t] = s4.w;
    }
    __syncthreads();

    int t0 = (tid >> 4) << 2, v0 = (tid & 15) << 2;
    float acc[4][4];
#pragma unroll
    for (int i = 0; i < 4; i++)
#pragma unroll
        for (int j = 0; j < 4; j++) acc[i][j] = 0.f;
    for (int k = 0; k < 64; k++) {
        float4 a = *(float4*)&sQt[k * PD + t0];
        float4 bb = *(float4*)&sSt[k * PD + v0];
        float av[4] = {a.x, a.y, a.z, a.w};
        float bv[4] = {bb.x, bb.y, bb.z, bb.w};
#pragma unroll
        for (int i = 0; i < 4; i++)
#pragma unroll
            for (int j = 0; j < 4; j++) acc[i][j] = fmaf(av[i], bv[j], acc[i][j]);
    }
#pragma unroll
    for (int i = 0; i < 4; i++) {
        int t = t0 + i;
        size_t gi = rowbase + (size_t)t * HIDK + v0;
        float4 e = *(float4*)(g_expD + gi);
        float4 o = *(float4*)(g_att + gi);
        o.x = fmaf(acc[i][0], e.x, o.x);
        o.y = fmaf(acc[i][1], e.y, o.y);
        o.z = fmaf(acc[i][2], e.z, o.z);
        o.w = fmaf(acc[i][3], e.w, o.w);
        *(float4*)(g_att + gi) = o;
    }
}

// ---------------- LayerNorm + SiLU output gate ------------------------------
__global__ void __launch_bounds__(256) ln_gate_kernel(const float* __restrict__ gamma,
                                                      const float* __restrict__ beta) {
    int row = blockIdx.x;
    int tid = threadIdx.x;
    const float* a = g_att + (size_t)row * HIDK;
    float vals[4];
    float s = 0.f, s2 = 0.f;
#pragma unroll
    for (int i = 0; i < 4; i++) {
        vals[i] = a[i * 256 + tid];
        s += vals[i];
        s2 = fmaf(vals[i], vals[i], s2);
    }
#pragma unroll
    for (int o = 16; o; o >>= 1) {
        s += __shfl_xor_sync(0xffffffffu, s, o);
        s2 += __shfl_xor_sync(0xffffffffu, s2, o);
    }
    __shared__ float rs[8], rs2[8];
    int warp = tid >> 5;
    if ((tid & 31) == 0) { rs[warp] = s; rs2[warp] = s2; }
    __syncthreads();
    s = 0.f; s2 = 0.f;
#pragma unroll
    for (int w = 0; w < 8; w++) { s += rs[w]; s2 += rs2[w]; }
    float mean = s * (1.f / HIDK);
    float var = s2 * (1.f / HIDK) - mean * mean;
    float rstd = rsqrtf(var + 1e-5f);
#pragma unroll
    for (int i = 0; i < 4; i++) {
        int col = i * 256 + tid;
        float gv = g_xg[(size_t)row * HIDK + col];
        float sil = gv / (1.f + __expf(-gv));
        g_y[(size_t)row * HIDK + col] =
            ((vals[i] - mean) * rstd * gamma[col] + beta[col]) * sil;
    }
}

// ---------------- launch --------------------------------------------------
extern "C" void kernel_launch(void* const* d_in, const int* in_sizes, int n_in,
                              void* d_out, int out_size) {
    const float* x = (const float*)d_in[0];
    const float* Wq = (const float*)d_in[1];
    const float* Wk = (const float*)d_in[2];
    const float* Wv = (const float*)d_in[3];
    const float* Wg = (const float*)d_in[4];
    const float* Wgk1 = (const float*)d_in[5];
    const float* Wgk2 = (const float*)d_in[6];
    const float* bgk2 = (const float*)d_in[7];
    const float* gamma = (const float*)d_in[8];
    const float* beta = (const float*)d_in[9];
    const float* Wout = (const float*)d_in[10];
    float* out = (float*)d_out;

    static int smem_set = 0;
    const int SMEM_A = 6 * 64 * PD * sizeof(float);
    if (!smem_set) {
        cudaFuncSetAttribute(chunk_kernel,
                             cudaFuncAttributeMaxDynamicSharedMemorySize, SMEM_A);
        smem_set = 1;
    }

    dim3 gridG(HIDK / BN, MTOK / BM, 4);
    sgemm4_kernel<<<gridG, 256>>>(x, Wq, Wk, Wv, Wg);
    lr1_kernel<<<MTOK / 16, 256>>>(x, Wgk1);
    lr2_kernel<<<MTOK, 256>>>(Wgk2, bgk2);
    chunk_kernel<<<dim3(NCH, 32), 256, SMEM_A>>>();
    chunkscan_kernel<<<32, 512>>>();
    inter_kernel<<<dim3(NCH, 32), 256>>>();
    ln_gate_kernel<<<MTOK, 256>>>(gamma, beta);
    dim3 gridO(HIDK / BN, MTOK / BM, 1);
    sgemm_out_kernel<<<gridO, 256>>>(Wout, out);
}

// round 4
// speedup vs baseline: 3.1746x; 1.9046x over previous
#include <cuda_runtime.h>
#include <cuda_bf16.h>
#include <math.h>
#include <stdint.h>

#define HIDK 1024
#define MTOK 4096
#define LSEQ 2048
#define NHEAD 16
#define HDIM 64
#define CT 64
#define NCH (LSEQ / CT)
#define PD 68

// ---------------- scratch (device globals; no allocations) ----------------
__device__ float g_q[MTOK * HIDK];
__device__ float g_k[MTOK * HIDK];
__device__ float g_v[MTOK * HIDK];
__device__ float g_xg[MTOK * HIDK];
__device__ float g_gk[MTOK * HIDK];
__device__ float g_att[MTOK * HIDK];
__device__ float g_t[MTOK * 16];
__device__ float g_expD[MTOK * HIDK];
__device__ float g_P[32 * NCH * HDIM * HDIM];
__device__ float g_S[32 * NCH * HDIM * HDIM];
// bf16 split operands
__device__ __align__(16) __nv_bfloat16 g_xh[MTOK * HIDK];
__device__ __align__(16) __nv_bfloat16 g_xl[MTOK * HIDK];
__device__ __align__(16) __nv_bfloat16 g_yh[MTOK * HIDK];
__device__ __align__(16) __nv_bfloat16 g_yl[MTOK * HIDK];
__device__ __align__(16) __nv_bfloat16 g_wh[5 * HIDK * HIDK];  // transposed [n][k]
__device__ __align__(16) __nv_bfloat16 g_wl[5 * HIDK * HIDK];

// ======================= helpers =======================
__device__ __forceinline__ uint32_t smem_u32(const void* p) {
    uint32_t a;
    asm("{ .reg .u64 t; cvta.to.shared.u64 t, %1; cvt.u32.u64 %0, t; }" : "=r"(a) : "l"(p));
    return a;
}
__device__ __forceinline__ void cpasync16(uint32_t s, const void* g) {
    asm volatile("cp.async.cg.shared.global [%0], [%1], 16;" ::"r"(s), "l"(g));
}
__device__ __forceinline__ void cpcommit() { asm volatile("cp.async.commit_group;"); }

__device__ __forceinline__ void ldmx4(uint32_t& r0, uint32_t& r1, uint32_t& r2,
                                      uint32_t& r3, uint32_t addr) {
    asm volatile("ldmatrix.sync.aligned.m8n8.x4.shared.b16 {%0,%1,%2,%3}, [%4];"
                 : "=r"(r0), "=r"(r1), "=r"(r2), "=r"(r3)
                 : "r"(addr));
}
__device__ __forceinline__ void mma16816(float* c, const uint32_t* a, const uint32_t* b) {
    asm volatile(
        "mma.sync.aligned.m16n8k16.row.col.f32.bf16.bf16.f32 "
        "{%0,%1,%2,%3}, {%4,%5,%6,%7}, {%8,%9}, {%0,%1,%2,%3};"
        : "+f"(c[0]), "+f"(c[1]), "+f"(c[2]), "+f"(c[3])
        : "r"(a[0]), "r"(a[1]), "r"(a[2]), "r"(a[3]), "r"(b[0]), "r"(b[1]));
}

// ======================= bf16 mma.sync GEMM =======================
// C[M,1024] = A(hi+lo)[M,1024] @ W(hi+lo)^T  via 3 split products.
// CTA tile 128x128, BK=32, 4-stage cp.async pipeline.
#define ROWB 80       // 32 bf16 (64B) + 16B pad per row
#define STG_A (128 * ROWB)
#define STG (2 * STG_A)          // 20480 bytes per stage
#define NSTG 4
#define SMEM_MM (NSTG * STG)     // 81920 bytes
#define NSTAGES 96               // 3 phases * (1024/32)

__device__ __forceinline__ void mm_issue(int s, uint32_t sb, int tid, int brow, int bcol,
                                         const __nv_bfloat16* Ah, const __nv_bfloat16* Al,
                                         const __nv_bfloat16* Bh, const __nv_bfloat16* Bl) {
    if (s < NSTAGES) {
        int p = s >> 5;
        int kk = (s & 31) << 5;
        const __nv_bfloat16* Ab = (p < 2) ? Ah : Al;
        const __nv_bfloat16* Bb = (p == 1) ? Bl : Bh;
        uint32_t st = sb + (uint32_t)(s & 3) * STG;
        int row = tid >> 2, cw = tid & 3;
        const char* ga = (const char*)(Ab + (size_t)(brow + row) * HIDK + kk + cw * 8);
        cpasync16(st + row * ROWB + cw * 16, ga);
        cpasync16(st + (row + 64) * ROWB + cw * 16, ga + (size_t)64 * HIDK * 2);
        const char* gb = (const char*)(Bb + (size_t)(bcol + row) * HIDK + kk + cw * 8);
        cpasync16(st + STG_A + row * ROWB + cw * 16, gb);
        cpasync16(st + STG_A + (row + 64) * ROWB + cw * 16, gb + (size_t)64 * HIDK * 2);
    }
    cpcommit();  // empty groups at tail keep the pending-count invariant
}

__device__ __forceinline__ void mma_gemm_body(const __nv_bfloat16* __restrict__ Ah,
                                              const __nv_bfloat16* __restrict__ Al,
                                              const __nv_bfloat16* __restrict__ Bh,
                                              const __nv_bfloat16* __restrict__ Bl,
                                              float* __restrict__ C) {
    extern __shared__ char sm_raw[];
    uint32_t sb = smem_u32(sm_raw);
    int tid = threadIdx.x, lane = tid & 31, wid = tid >> 5;
    int wm = wid & 3, wn = wid >> 2;
    int brow = blockIdx.y * 128, bcol = blockIdx.x * 128;

    float c[2][8][4];
#pragma unroll
    for (int i = 0; i < 2; i++)
#pragma unroll
        for (int j = 0; j < 8; j++)
#pragma unroll
            for (int l = 0; l < 4; l++) c[i][j][l] = 0.f;

    mm_issue(0, sb, tid, brow, bcol, Ah, Al, Bh, Bl);
    mm_issue(1, sb, tid, brow, bcol, Ah, Al, Bh, Bl);
    mm_issue(2, sb, tid, brow, bcol, Ah, Al, Bh, Bl);

    int q = lane >> 3, r = lane & 7;

    for (int s = 0; s < NSTAGES; s++) {
        asm volatile("cp.async.wait_group 2;" ::: "memory");
        __syncthreads();
        uint32_t st = sb + (uint32_t)(s & 3) * STG;
        uint32_t sA = st, sB = st + STG_A;
#pragma unroll
        for (int k0 = 0; k0 < 32; k0 += 16) {
            uint32_t a[2][4], b[8][2];
#pragma unroll
            for (int mf = 0; mf < 2; mf++) {
                int rrow = wm * 32 + mf * 16 + (q & 1) * 8 + r;
                int kc = k0 + (q >> 1) * 8;
                ldmx4(a[mf][0], a[mf][1], a[mf][2], a[mf][3], sA + rrow * ROWB + kc * 2);
            }
#pragma unroll
            for (int pb = 0; pb < 4; pb++) {
                int nrow = wn * 64 + pb * 16 + (q >> 1) * 8 + r;
                int kc = k0 + (q & 1) * 8;
                uint32_t r0, r1, r2, r3;
                ldmx4(r0, r1, r2, r3, sB + nrow * ROWB + kc * 2);
                b[pb * 2][0] = r0;
                b[pb * 2][1] = r1;
                b[pb * 2 + 1][0] = r2;
                b[pb * 2 + 1][1] = r3;
            }
#pragma unroll
            for (int mf = 0; mf < 2; mf++)
#pragma unroll
                for (int nf = 0; nf < 8; nf++) mma16816(c[mf][nf], a[mf], b[nf]);
        }
        mm_issue(s + 3, sb, tid, brow, bcol, Ah, Al, Bh, Bl);
    }

    int qr = lane >> 2, qc = lane & 3;
#pragma unroll
    for (int mf = 0; mf < 2; mf++)
#pragma unroll
        for (int nf = 0; nf < 8; nf++) {
            int row0 = brow + wm * 32 + mf * 16 + qr;
            int col = bcol + wn * 64 + nf * 8 + qc * 2;
            *(float2*)&C[(size_t)row0 * HIDK + col] = make_float2(c[mf][nf][0], c[mf][nf][1]);
            *(float2*)&C[(size_t)(row0 + 8) * HIDK + col] = make_float2(c[mf][nf][2], c[mf][nf][3]);
        }
}

__global__ void __launch_bounds__(256, 2) mmproj_kernel() {
    int z = blockIdx.z;
    const __nv_bfloat16* Bh = g_wh + (size_t)z * HIDK * HIDK;
    const __nv_bfloat16* Bl = g_wl + (size_t)z * HIDK * HIDK;
    float* C = (z == 0) ? g_q : (z == 1) ? g_k : (z == 2) ? g_v : g_xg;
    mma_gemm_body(g_xh, g_xl, Bh, Bl, C);
}
__global__ void __launch_bounds__(256, 2) mmout_kernel(float* __restrict__ out) {
    mma_gemm_body(g_yh, g_yl, g_wh + (size_t)4 * HIDK * HIDK,
                  g_wl + (size_t)4 * HIDK * HIDK, out);
}

// ======================= conversion kernels =======================
__global__ void __launch_bounds__(256) xconv_kernel(const float* __restrict__ x) {
    size_t i = (size_t)blockIdx.x * 256 + threadIdx.x;
    float4 v = ((const float4*)x)[i];
    __nv_bfloat16 h0 = __float2bfloat16(v.x), h1 = __float2bfloat16(v.y);
    __nv_bfloat16 h2 = __float2bfloat16(v.z), h3 = __float2bfloat16(v.w);
    __nv_bfloat162* ph = (__nv_bfloat162*)g_xh;
    __nv_bfloat162* pl = (__nv_bfloat162*)g_xl;
    ph[2 * i] = __nv_bfloat162(h0, h1);
    ph[2 * i + 1] = __nv_bfloat162(h2, h3);
    pl[2 * i] = __nv_bfloat162(__float2bfloat16(v.x - __bfloat162float(h0)),
                               __float2bfloat16(v.y - __bfloat162float(h1)));
    pl[2 * i + 1] = __nv_bfloat162(__float2bfloat16(v.z - __bfloat162float(h2)),
                                   __float2bfloat16(v.w - __bfloat162float(h3)));
}

// transpose + split: Wt[n][k] = W[k][n]
__global__ void __launch_bounds__(256) wconv_kernel(const float* __restrict__ W0,
                                                    const float* __restrict__ W1,
                                                    const float* __restrict__ W2,
                                                    const float* __restrict__ W3,
                                                    const float* __restrict__ W4) {
    int z = blockIdx.z;
    const float* W = (z == 0) ? W0 : (z == 1) ? W1 : (z == 2) ? W2 : (z == 3) ? W3 : W4;
    __nv_bfloat16* Th = g_wh + (size_t)z * HIDK * HIDK;
    __nv_bfloat16* Tl = g_wl + (size_t)z * HIDK * HIDK;
    __shared__ float t[32][33];
    int n0 = blockIdx.x * 32, k0 = blockIdx.y * 32;
    int lx = threadIdx.x & 31, ly = threadIdx.x >> 5;
#pragma unroll
    for (int i = 0; i < 4; i++) {
        int r = ly + i * 8;
        t[r][lx] = W[(size_t)(k0 + r) * HIDK + n0 + lx];
    }
    __syncthreads();
#pragma unroll
    for (int i = 0; i < 4; i++) {
        int r = ly + i * 8;
        float v = t[lx][r];  // = W[k0+lx][n0+r]
        __nv_bfloat16 h = __float2bfloat16(v);
        size_t o = (size_t)(n0 + r) * HIDK + k0 + lx;
        Th[o] = h;
        Tl[o] = __float2bfloat16(v - __bfloat162float(h));
    }
}

// ---------------- low-rank gate path ---------------------------------------
__global__ void __launch_bounds__(256) lr1_kernel(const float* __restrict__ x,
                                                  const float* __restrict__ W1) {
    int tid = threadIdx.x;
    int r = tid & 15;
    int ml = tid >> 4;
    int m = blockIdx.x * 16 + ml;
    const float* xr = x + (size_t)m * HIDK;
    float acc = 0.f;
#pragma unroll 4
    for (int kk = 0; kk < HIDK; kk++) acc = fmaf(xr[kk], W1[kk * 16 + r], acc);
    g_t[m * 16 + r] = acc;
}

__global__ void __launch_bounds__(256) lr2_kernel(const float* __restrict__ W2,
                                                  const float* __restrict__ bias) {
    int m = blockIdx.x;
    __shared__ float tm[16];
    if (threadIdx.x < 16) tm[threadIdx.x] = g_t[m * 16 + threadIdx.x];
    __syncthreads();
    for (int n = threadIdx.x; n < HIDK; n += 256) {
        float a = bias[n];
#pragma unroll
        for (int r = 0; r < 16; r++) a = fmaf(tm[r], W2[r * HIDK + n], a);
        float ls = fminf(a, 0.f) - log1pf(__expf(-fabsf(a)));
        g_gk[(size_t)m * HIDK + n] = ls * 0.0625f;
    }
}

// ---------------- chunked GLA: kernel A (intra-chunk + summaries) ----------
__global__ void __launch_bounds__(256) chunk_kernel() {
    extern __shared__ float sm[];
    float* sQt = sm;
    float* sKt = sm + 64 * PD;
    float* sK = sm + 2 * 64 * PD;
    float* sU = sm + 3 * 64 * PD;
    float* sAV = sm + 4 * 64 * PD;
    float* sED = sm + 5 * 64 * PD;

    int c = blockIdx.x, bh = blockIdx.y;
    int b = bh >> 4, h = bh & 15;
    int tid = threadIdx.x;
    size_t rowbase = (size_t)(b * LSEQ + c * CT) * HIDK + h * HDIM;

#pragma unroll
    for (int i = 0; i < 4; i++) {
        int idx = tid + i * 256;
        int t = idx >> 4, c4 = (idx & 15) << 2;
        size_t gi = rowbase + (size_t)t * HIDK + c4;
        float4 q4 = *(const float4*)(g_q + gi);
        float4 k4 = *(const float4*)(g_k + gi);
        float4 v4 = *(const float4*)(g_v + gi);
        float4 gg = *(const float4*)(g_gk + gi);
        sQt[(c4 + 0) * PD + t] = q4.x;
        sQt[(c4 + 1) * PD + t] = q4.y;
        sQt[(c4 + 2) * PD + t] = q4.z;
        sQt[(c4 + 3) * PD + t] = q4.w;
        sKt[(c4 + 0) * PD + t] = k4.x;
        sKt[(c4 + 1) * PD + t] = k4.y;
        sKt[(c4 + 2) * PD + t] = k4.z;
        sKt[(c4 + 3) * PD + t] = k4.w;
        *(float4*)&sK[t * PD + c4] = k4;
        *(float4*)&sAV[t * PD + c4] = v4;
        *(float4*)&sED[t * PD + c4] = gg;
    }
    __syncthreads();

    if (tid < 64) {
        float run = 0.f;
        for (int t = 0; t < CT; t++) {
            run += sED[t * PD + tid];
            sED[t * PD + tid] = __expf(run);
            sU[t * PD + tid] = __expf(-run) * sAV[t * PD + tid];
        }
    }
    __syncthreads();

#pragma unroll
    for (int i = 0; i < 4; i++) {
        int idx = tid + i * 256;
        int t = idx >> 4, c4 = (idx & 15) << 2;
        *(float4*)(g_expD + rowbase + (size_t)t * HIDK + c4) = *(float4*)&sED[t * PD + c4];
    }

    {
        int t0 = (tid & 15) << 2, s0 = (tid >> 4) << 2;
        float acc[4][4];
#pragma unroll
        for (int i = 0; i < 4; i++)
#pragma unroll
            for (int j = 0; j < 4; j++) acc[i][j] = 0.f;
        for (int d = 0; d < 64; d++) {
            float4 a = *(float4*)&sQt[d * PD + t0];
            float4 bb = *(float4*)&sKt[d * PD + s0];
            float av[4] = {a.x, a.y, a.z, a.w};
            float bv[4] = {bb.x, bb.y, bb.z, bb.w};
#pragma unroll
            for (int i = 0; i < 4; i++)
#pragma unroll
                for (int j = 0; j < 4; j++) acc[i][j] = fmaf(av[i], bv[j], acc[i][j]);
        }
#pragma unroll
        for (int j = 0; j < 4; j++) {
            int s = s0 + j;
            float4 o;
            o.x = (s <= t0 + 0) ? acc[0][j] : 0.f;
            o.y = (s <= t0 + 1) ? acc[1][j] : 0.f;
            o.z = (s <= t0 + 2) ? acc[2][j] : 0.f;
            o.w = (s <= t0 + 3) ? acc[3][j] : 0.f;
            *(float4*)&sAV[s * PD + t0] = o;
        }
    }
    __syncthreads();

    int r0 = (tid >> 4) << 2, c0 = (tid & 15) << 2;

    {
        float acc[4][4];
#pragma unroll
        for (int i = 0; i < 4; i++)
#pragma unroll
            for (int j = 0; j < 4; j++) acc[i][j] = 0.f;
        for (int s = 0; s < CT; s++) {
            float4 a = *(float4*)&sAV[s * PD + r0];
            float4 bb = *(float4*)&sU[s * PD + c0];
            float av[4] = {a.x, a.y, a.z, a.w};
            float bv[4] = {bb.x, bb.y, bb.z, bb.w};
#pragma unroll
            for (int i = 0; i < 4; i++)
#pragma unroll
                for (int j = 0; j < 4; j++) acc[i][j] = fmaf(av[i], bv[j], acc[i][j]);
        }
#pragma unroll
        for (int i = 0; i < 4; i++) {
            int t = r0 + i;
            float4 e = *(float4*)&sED[t * PD + c0];
            float4 o = make_float4(acc[i][0] * e.x, acc[i][1] * e.y, acc[i][2] * e.z,
                                   acc[i][3] * e.w);
            *(float4*)(g_att + rowbase + (size_t)t * HIDK + c0) = o;
        }
    }

    {
        float acc[4][4];
#pragma unroll
        for (int i = 0; i < 4; i++)
#pragma unroll
            for (int j = 0; j < 4; j++) acc[i][j] = 0.f;
        for (int s = 0; s < CT; s++) {
            float4 a = *(float4*)&sU[s * PD + r0];
            float4 bb = *(float4*)&sK[s * PD + c0];
            float av[4] = {a.x, a.y, a.z, a.w};
            float bv[4] = {bb.x, bb.y, bb.z, bb.w};
#pragma unroll
            for (int i = 0; i < 4; i++)
#pragma unroll
                for (int j = 0; j < 4; j++) acc[i][j] = fmaf(av[i], bv[j], acc[i][j]);
        }
        size_t pbase = ((size_t)(bh * NCH + c)) << 12;
#pragma unroll
        for (int i = 0; i < 4; i++) {
            float ev = sED[63 * PD + r0 + i];
            float4 o = make_float4(acc[i][0] * ev, acc[i][1] * ev, acc[i][2] * ev,
                                   acc[i][3] * ev);
            *(float4*)(g_P + pbase + ((size_t)(r0 + i) << 6) + c0) = o;
        }
    }
}

// ---------------- kernel B: scan over chunk states --------------------------
__global__ void __launch_bounds__(512) chunkscan_kernel() {
    int bh = blockIdx.x;
    int b = bh >> 4, h = bh & 15;
    int tid = threadIdx.x;
    int v = tid >> 3;
    int k0 = (tid & 7) << 3;
    float S[8];
#pragma unroll
    for (int j = 0; j < 8; j++) S[j] = 0.f;

    for (int c = 0; c < NCH; c++) {
        size_t base = (((size_t)(bh * NCH + c)) << 12) + ((size_t)v << 6) + k0;
        *(float4*)(g_S + base) = make_float4(S[0], S[1], S[2], S[3]);
        *(float4*)(g_S + base + 4) = make_float4(S[4], S[5], S[6], S[7]);
        float E = g_expD[((size_t)(b * LSEQ + c * CT + 63)) * HIDK + h * HDIM + v];
        float4 p0 = *(float4*)(g_P + base);
        float4 p1 = *(float4*)(g_P + base + 4);
        S[0] = fmaf(S[0], E, p0.x);
        S[1] = fmaf(S[1], E, p0.y);
        S[2] = fmaf(S[2], E, p0.z);
        S[3] = fmaf(S[3], E, p0.w);
        S[4] = fmaf(S[4], E, p1.x);
        S[5] = fmaf(S[5], E, p1.y);
        S[6] = fmaf(S[6], E, p1.z);
        S[7] = fmaf(S[7], E, p1.w);
    }
}

// ---------------- kernel C: inter-chunk output ------------------------------
__global__ void __launch_bounds__(256) inter_kernel() {
    __shared__ float sQt[64 * PD];
    __shared__ float sSt[64 * PD];
    int c = blockIdx.x, bh = blockIdx.y;
    int b = bh >> 4, h = bh & 15;
    int tid = threadIdx.x;
    size_t rowbase = (size_t)(b * LSEQ + c * CT) * HIDK + h * HDIM;
    size_t sbase = ((size_t)(bh * NCH + c)) << 12;

#pragma unroll
    for (int i = 0; i < 4; i++) {
        int idx = tid + i * 256;
        int t = idx >> 4, c4 = (idx & 15) << 2;
        float4 q4 = *(const float4*)(g_q + rowbase + (size_t)t * HIDK + c4);
        sQt[(c4 + 0) * PD + t] = q4.x;
        sQt[(c4 + 1) * PD + t] = q4.y;
        sQt[(c4 + 2) * PD + t] = q4.z;
        sQt[(c4 + 3) * PD + t] = q4.w;
        float4 s4 = *(const float4*)(g_S + sbase + ((size_t)t << 6) + c4);
        sSt[(c4 + 0) * PD + t] = s4.x;
        sSt[(c4 + 1) * PD + t] = s4.y;
        sSt[(c4 + 2) * PD + t] = s4.z;
        sSt[(c4 + 3) * PD + t] = s4.w;
    }
    __syncthreads();

    int t0 = (tid >> 4) << 2, v0 = (tid & 15) << 2;
    float acc[4][4];
#pragma unroll
    for (int i = 0; i < 4; i++)
#pragma unroll
        for (int j = 0; j < 4; j++) acc[i][j] = 0.f;
    for (int k = 0; k < 64; k++) {
        float4 a = *(float4*)&sQt[k * PD + t0];
        float4 bb = *(float4*)&sSt[k * PD + v0];
        float av[4] = {a.x, a.y, a.z, a.w};
        float bv[4] = {bb.x, bb.y, bb.z, bb.w};
#pragma unroll
        for (int i = 0; i < 4; i++)
#pragma unroll
            for (int j = 0; j < 4; j++) acc[i][j] = fmaf(av[i], bv[j], acc[i][j]);
    }
#pragma unroll
    for (int i = 0; i < 4; i++) {
        int t = t0 + i;
        size_t gi = rowbase + (size_t)t * HIDK + v0;
        float4 e = *(float4*)(g_expD + gi);
        float4 o = *(float4*)(g_att + gi);
        o.x = fmaf(acc[i][0], e.x, o.x);
        o.y = fmaf(acc[i][1], e.y, o.y);
        o.z = fmaf(acc[i][2], e.z, o.z);
        o.w = fmaf(acc[i][3], e.w, o.w);
        *(float4*)(g_att + gi) = o;
    }
}

// ---------------- LayerNorm + SiLU gate -> bf16-split y ---------------------
__global__ void __launch_bounds__(256) ln_gate_kernel(const float* __restrict__ gamma,
                                                      const float* __restrict__ beta) {
    int row = blockIdx.x;
    int tid = threadIdx.x;
    const float* a = g_att + (size_t)row * HIDK;
    float vals[4];
    float s = 0.f, s2 = 0.f;
#pragma unroll
    for (int i = 0; i < 4; i++) {
        vals[i] = a[i * 256 + tid];
        s += vals[i];
        s2 = fmaf(vals[i], vals[i], s2);
    }
#pragma unroll
    for (int o = 16; o; o >>= 1) {
        s += __shfl_xor_sync(0xffffffffu, s, o);
        s2 += __shfl_xor_sync(0xffffffffu, s2, o);
    }
    __shared__ float rs[8], rs2[8];
    int warp = tid >> 5;
    if ((tid & 31) == 0) { rs[warp] = s; rs2[warp] = s2; }
    __syncthreads();
    s = 0.f;
    s2 = 0.f;
#pragma unroll
    for (int w = 0; w < 8; w++) { s += rs[w]; s2 += rs2[w]; }
    float mean = s * (1.f / HIDK);
    float var = s2 * (1.f / HIDK) - mean * mean;
    float rstd = rsqrtf(var + 1e-5f);
#pragma unroll
    for (int i = 0; i < 4; i++) {
        int col = i * 256 + tid;
        float gv = g_xg[(size_t)row * HIDK + col];
        float sil = gv / (1.f + __expf(-gv));
        float yv = ((vals[i] - mean) * rstd * gamma[col] + beta[col]) * sil;
        __nv_bfloat16 h = __float2bfloat16(yv);
        g_yh[(size_t)row * HIDK + col] = h;
        g_yl[(size_t)row * HIDK + col] = __float2bfloat16(yv - __bfloat162float(h));
    }
}

// ---------------- launch --------------------------------------------------
extern "C" void kernel_launch(void* const* d_in, const int* in_sizes, int n_in,
                              void* d_out, int out_size) {
    const float* x = (const float*)d_in[0];
    const float* Wq = (const float*)d_in[1];
    const float* Wk = (const float*)d_in[2];
    const float* Wv = (const float*)d_in[3];
    const float* Wg = (const float*)d_in[4];
    const float* Wgk1 = (const float*)d_in[5];
    const float* Wgk2 = (const float*)d_in[6];
    const float* bgk2 = (const float*)d_in[7];
    const float* gamma = (const float*)d_in[8];
    const float* beta = (const float*)d_in[9];
    const float* Wout = (const float*)d_in[10];
    float* out = (float*)d_out;

    const int SMEM_A = 6 * 64 * PD * sizeof(float);
    cudaFuncSetAttribute(chunk_kernel, cudaFuncAttributeMaxDynamicSharedMemorySize, SMEM_A);
    cudaFuncSetAttribute(mmproj_kernel, cudaFuncAttributeMaxDynamicSharedMemorySize, SMEM_MM);
    cudaFuncSetAttribute(mmout_kernel, cudaFuncAttributeMaxDynamicSharedMemorySize, SMEM_MM);

    xconv_kernel<<<MTOK * HIDK / 1024, 256>>>(x);
    wconv_kernel<<<dim3(32, 32, 5), 256>>>(Wq, Wk, Wv, Wg, Wout);
    lr1_kernel<<<MTOK / 16, 256>>>(x, Wgk1);
    lr2_kernel<<<MTOK, 256>>>(Wgk2, bgk2);

    mmproj_kernel<<<dim3(8, 32, 4), 256, SMEM_MM>>>();

    chunk_kernel<<<dim3(NCH, 32), 256, SMEM_A>>>();
    chunkscan_kernel<<<32, 512>>>();
    inter_kernel<<<dim3(NCH, 32), 256>>>();
    ln_gate_kernel<<<MTOK, 256>>>(gamma, beta);

    mmout_kernel<<<dim3(8, 32, 1), 256, SMEM_MM>>>(out);
}